// round 11
// baseline (speedup 1.0000x reference)
#include <cuda_runtime.h>
#include <cuda_bf16.h>
#include <cstdint>
#include <mma.h>
using namespace nvcuda;

#define NB 32
#define NV 197
#define NVP 256
#define NT 512
#define ND 768
#define NM (NB*NT)       // 16384
#define NNB 12           // n-blocks in gemm_h (768/64)
#define NCH 13           // conv row-chunks of 16

// ---------------- device scratch ----------------
static __device__ float g_amap[NB*NVP*NT];
static __device__ float g_tapart[NCH*NB*NT];
static __device__ float g_ta[NM];
static __device__ float g_va[NB*NV];
static __device__ float g_vcls[NB*ND];
static __device__ float g_tcls[NB*ND];
static __device__ float g_temb[NB*ND];
static __device__ float g_vemb[NB*ND];
static __device__ float g_predpart[NNB*NM];
static __device__ float g_keff[9][25];
static __device__ float g_kbias[9];
static __device__ __nv_bfloat16 g_textbf[NM*ND];
static __device__ __nv_bfloat16 g_visbf[NB*NV*ND];
static __device__ __nv_bfloat16 g_w1bf[ND*ND];

__device__ __forceinline__ float wred(float v){
#pragma unroll
    for (int o = 16; o; o >>= 1) v += __shfl_xor_sync(0xffffffffu, v, o);
    return v;
}
__device__ __forceinline__ float sigmoidf(float x){ return 1.f/(1.f + expf(-x)); }

// ---- cp.async helpers ----
__device__ __forceinline__ void cp16(void* s, const void* g){
    unsigned int sa = (unsigned int)__cvta_generic_to_shared(s);
    asm volatile("cp.async.cg.shared.global [%0], [%1], 16;" :: "r"(sa), "l"(g));
}
__device__ __forceinline__ void cp_commit(){ asm volatile("cp.async.commit_group;"); }
template<int N> __device__ __forceinline__ void cp_wait(){
    asm volatile("cp.async.wait_group %0;" :: "n"(N));
}

// BK=64 tile geometry: stride 72 bf16 (=144B, conflict-free LDSM row spread)
#define TSTR 72
#define TILE_A (128*TSTR)                   // A tile elements per stage
#define TILE_B (64*TSTR)                    // B tile elements per stage
#define STAGE_ELE (TILE_A + TILE_B)
#define G_DYN (2*STAGE_ELE*2)               // 55,296 B dynamic smem per GEMM block

// ---------------- fp32 -> bf16 conversion + conv composition (merged) ----------------
#define CT1 (NM*ND/4)
#define CT2 (CT1 + NB*NV*ND/4)
#define CT3 (CT2 + ND*ND/4)
#define NCVT (CT3/256)
__global__ void convert_prep_kernel(const float* __restrict__ text,
                                    const float* __restrict__ vision,
                                    const float* __restrict__ fc1w,
                                    const float* __restrict__ w1, const float* __restrict__ b1,
                                    const float* __restrict__ w2, const float* __restrict__ b2){
    if (blockIdx.x < NCVT){
        int p = blockIdx.x*256 + threadIdx.x;
        const float* src; __nv_bfloat16* dst; int off;
        if (p < CT1){ src = text; dst = g_textbf; off = p; }
        else if (p < CT2){ src = vision; dst = g_visbf; off = p - CT1; }
        else { src = fc1w; dst = g_w1bf; off = p - CT2; }
        float4 v = ((const float4*)src)[off];
        __nv_bfloat162* d2 = (__nv_bfloat162*)dst;
        d2[off*2]   = __floats2bfloat162_rn(v.x, v.y);
        d2[off*2+1] = __floats2bfloat162_rn(v.z, v.w);
        return;
    }
    int tid = threadIdx.x;
    if (tid < 225){
        int var = tid/25, uv = tid%25, u = uv/5, v = uv%5;
        int ri = var/3, rj = var%3;
        float s = 0.f;
        for (int d1=0; d1<3; d1++){
            if ((ri==0 && d1==0) || (ri==2 && d1==2)) continue;
            int d2 = u - d1; if (d2 < 0 || d2 > 2) continue;
            for (int e1=0; e1<3; e1++){
                if ((rj==0 && e1==0) || (rj==2 && e1==2)) continue;
                int e2 = v - e1; if (e2 < 0 || e2 > 2) continue;
                for (int c=0; c<64; c++)
                    s += w2[c*9 + d1*3 + e1] * w1[c*9 + d2*3 + e2];
            }
        }
        g_keff[var][uv] = s;
    } else if (tid < 234){
        int var = tid - 225;
        int ri = var/3, rj = var%3;
        float s = b2[0];
        for (int c=0; c<64; c++){
            float t = 0.f;
            for (int d1=0; d1<3; d1++){
                if ((ri==0 && d1==0) || (ri==2 && d1==2)) continue;
                for (int e1=0; e1<3; e1++){
                    if ((rj==0 && e1==0) || (rj==2 && e1==2)) continue;
                    t += w2[c*9 + d1*3 + e1];
                }
            }
            s += b1[c]*t;
        }
        g_kbias[var] = s;
    }
}

// ============ bf16 wmma GEMM 1 (128x64 tile, occ3): amap = vision . text^T ============
__global__ __launch_bounds__(256,3) void gemm_amap_kernel(){
    extern __shared__ __align__(16) __nv_bfloat16 dynbf[];
    int b  = blockIdx.z;
    const __nv_bfloat16* A  = g_visbf  + (size_t)b*NV*ND;
    const __nv_bfloat16* Bp = g_textbf + (size_t)b*NT*ND;
    int m0 = blockIdx.x*128, n0 = blockIdx.y*64;
    int tid = threadIdx.x, wid = tid >> 5;
    int warp_m = wid >> 1, warp_n = wid & 1;

    wmma::fragment<wmma::accumulator,16,16,16,float> acc[2][2];
#pragma unroll
    for (int mf=0;mf<2;mf++)
#pragma unroll
        for (int nf=0;nf<2;nf++) wmma::fill_fragment(acc[mf][nf], 0.f);

    const int NKT = ND/64;   // 12
#define AMAP_LOAD(s, k0)  do {                                               \
    __nv_bfloat16* As_ = dynbf + (size_t)(s)*STAGE_ELE;                      \
    __nv_bfloat16* Bs_ = As_ + TILE_A;                                       \
    _Pragma("unroll")                                                        \
    for (int l=0; l<4; l++){                                                 \
        int q = tid + l*256;                                                 \
        int r = q >> 3, c8 = q & 7;                                          \
        int gm = m0 + r; if (gm > NV-1) gm = NV-1;                           \
        cp16(&As_[r*TSTR + c8*8], &A[(size_t)gm*ND + (k0) + c8*8]);          \
    }                                                                        \
    _Pragma("unroll")                                                        \
    for (int l=0; l<2; l++){                                                 \
        int q = tid + l*256;                                                 \
        int r = q >> 3, c8 = q & 7;                                          \
        cp16(&Bs_[r*TSTR + c8*8], &Bp[(size_t)(n0+r)*ND + (k0) + c8*8]);     \
    } } while(0)

    AMAP_LOAD(0, 0);
    cp_commit();
    for (int kt=0; kt<NKT; kt++){
        cp_wait<0>();
        __syncthreads();
        if (kt+1 < NKT){ AMAP_LOAD((kt+1)&1, (kt+1)*64); cp_commit(); }
        const __nv_bfloat16* As = dynbf + (size_t)(kt&1)*STAGE_ELE;
        const __nv_bfloat16* Bs = As + TILE_A;
#pragma unroll
        for (int ks=0; ks<4; ks++){
            wmma::fragment<wmma::matrix_a,16,16,16,__nv_bfloat16,wmma::row_major> af[2];
            wmma::fragment<wmma::matrix_b,16,16,16,__nv_bfloat16,wmma::col_major> bf[2];
#pragma unroll
            for (int mf=0;mf<2;mf++)
                wmma::load_matrix_sync(af[mf], &As[(warp_m*32+mf*16)*TSTR + ks*16], TSTR);
#pragma unroll
            for (int nf=0;nf<2;nf++)
                wmma::load_matrix_sync(bf[nf], &Bs[(warp_n*32+nf*16)*TSTR + ks*16], TSTR);
#pragma unroll
            for (int mf=0;mf<2;mf++)
#pragma unroll
                for (int nf=0;nf<2;nf++)
                    wmma::mma_sync(acc[mf][nf], af[mf], bf[nf], acc[mf][nf]);
        }
    }
#undef AMAP_LOAD
    float* C = g_amap + (size_t)b*NVP*NT;
#pragma unroll
    for (int mf=0;mf<2;mf++)
#pragma unroll
        for (int nf=0;nf<2;nf++)
            wmma::store_matrix_sync(&C[(size_t)(m0+warp_m*32+mf*16)*NT + n0+warp_n*32+nf*16],
                                    acc[mf][nf], NT, wmma::mem_row_major);
}

// ============ fused 5x5 conv + relu + va + ta partials ============
__global__ __launch_bounds__(256) void conv_fused_kernel(){
    __shared__ float smz[20][NT];
    __shared__ float kvs[9][25];
    __shared__ float kbs[9];
    __shared__ float rowred[16][8];
    int c = blockIdx.x;
    int b = blockIdx.y;
    int tid = threadIdx.x;
    int warp = tid >> 5, lane = tid & 31;
    if (tid < 225) ((float*)kvs)[tid] = ((const float*)g_keff)[tid];
    else if (tid >= 240 && tid < 249) kbs[tid-240] = g_kbias[tid-240];

    int i0 = c*16;
    const float* base = g_amap + (size_t)b*NVP*NT;
#pragma unroll
    for (int l=0; l<10; l++){
        int e = tid + l*256;
        int rr = e >> 7, c4 = e & 127;
        int gi = i0 - 2 + rr;
        float4 v = make_float4(0.f,0.f,0.f,0.f);
        if (gi >= 0 && gi < NV) v = *(const float4*)&base[(size_t)gi*NT + c4*4];
        *(float4*)&smz[rr][c4*4] = v;
    }
    __syncthreads();

    float rowpart[16];
#pragma unroll
    for (int rr=0;rr<16;rr++) rowpart[rr] = 0.f;

#pragma unroll
    for (int jj=0; jj<2; jj++){
        int j = tid + jj*256;
        int rj = (j==0) ? 0 : ((j==NT-1) ? 2 : 1);
        float kreg[25];
#pragma unroll
        for (int t=0;t<25;t++) kreg[t] = kvs[3+rj][t];
        float kbmid = kbs[3+rj];

        float w[5][5];
#pragma unroll
        for (int u=0;u<4;u++)
#pragma unroll
            for (int v=0;v<5;v++){
                int j2 = j + v - 2;
                w[u][v] = (j2>=0 && j2<NT) ? smz[u][j2] : 0.f;
            }
        float colsum = 0.f;
#pragma unroll
        for (int rr=0; rr<16; rr++){
#pragma unroll
            for (int v=0;v<5;v++){
                int j2 = j + v - 2;
                w[4][v] = (j2>=0 && j2<NT) ? smz[rr+4][j2] : 0.f;
            }
            int i = i0 + rr;
            if (i < NV){
                float s;
                if (i==0 || i==NV-1){
                    int var = ((i==0)?0:6) + rj;
                    s = kbs[var];
                    const float* kp = kvs[var];
#pragma unroll
                    for (int u=0;u<5;u++)
#pragma unroll
                        for (int v=0;v<5;v++) s += kp[u*5+v]*w[u][v];
                } else {
                    s = kbmid;
#pragma unroll
                    for (int u=0;u<5;u++)
#pragma unroll
                        for (int v=0;v<5;v++) s += kreg[u*5+v]*w[u][v];
                }
                s = fmaxf(s, 0.f);
                colsum += s;
                rowpart[rr] += s;
            }
#pragma unroll
            for (int u=0;u<4;u++)
#pragma unroll
                for (int v=0;v<5;v++) w[u][v] = w[u+1][v];
        }
        g_tapart[(size_t)(c*NB + b)*NT + j] = colsum;
    }
#pragma unroll
    for (int rr=0; rr<16; rr++){
        float v = wred(rowpart[rr]);
        if (lane == 0) rowred[rr][warp] = v;
    }
    __syncthreads();
    if (tid < 128){
        int rr = tid >> 3, slot = tid & 7;
        float v = rowred[rr][slot];
        v += __shfl_down_sync(0xffffffffu, v, 4, 8);
        v += __shfl_down_sync(0xffffffffu, v, 2, 8);
        v += __shfl_down_sync(0xffffffffu, v, 1, 8);
        if (slot == 0){
            int gi = i0 + rr;
            if (gi < NV) g_va[b*NV + gi] = sigmoidf(v * (1.f/(float)NT));
        }
    }
}

// ============ bf16 wmma GEMM 2 (128x64 tile, occ3) + inline ta + pred epilogue ============
__global__ __launch_bounds__(256,3) void gemm_h_kernel(const float* __restrict__ fc1b,
                                                       const float* __restrict__ fc2w){
    extern __shared__ __align__(16) __nv_bfloat16 dynbf[];
    __shared__ float sta[128];
    int m0 = blockIdx.x*128, n0 = blockIdx.y*64;
    int tid = threadIdx.x, wid = tid >> 5;
    int warp_m = wid >> 1, warp_n = wid & 1;

    // inline ta for this block's 128 rows (from conv column partials)
    {
        int bb = m0 / NT, t0 = m0 % NT;
        if (tid < 128){
            float s = 0.f;
#pragma unroll
            for (int c=0;c<NCH;c++) s += g_tapart[(size_t)(c*NB + bb)*NT + t0 + tid];
            float v = sigmoidf(s * (1.f/(float)NV));
            sta[tid] = v;
            if (blockIdx.y == 0) g_ta[m0 + tid] = v;
        }
    }

    wmma::fragment<wmma::accumulator,16,16,16,float> acc[2][2];
#pragma unroll
    for (int mf=0;mf<2;mf++)
#pragma unroll
        for (int nf=0;nf<2;nf++) wmma::fill_fragment(acc[mf][nf], 0.f);

    const int NKT = ND/64;   // 12
#define H_LOAD(s, k0)  do {                                                    \
    __nv_bfloat16* As_ = dynbf + (size_t)(s)*STAGE_ELE;                        \
    __nv_bfloat16* Bs_ = As_ + TILE_A;                                         \
    _Pragma("unroll")                                                          \
    for (int l=0; l<4; l++){                                                   \
        int q = tid + l*256;                                                   \
        int r = q >> 3, c8 = q & 7;                                            \
        cp16(&As_[r*TSTR + c8*8], &g_textbf[(size_t)(m0+r)*ND + (k0) + c8*8]); \
    }                                                                          \
    _Pragma("unroll")                                                          \
    for (int l=0; l<2; l++){                                                   \
        int q = tid + l*256;                                                   \
        int r = q >> 3, c8 = q & 7;                                            \
        cp16(&Bs_[r*TSTR + c8*8], &g_w1bf[(size_t)(n0+r)*ND + (k0) + c8*8]);   \
    } } while(0)

    H_LOAD(0, 0);
    cp_commit();
    for (int kt=0; kt<NKT; kt++){
        cp_wait<0>();
        __syncthreads();
        if (kt+1 < NKT){ H_LOAD((kt+1)&1, (kt+1)*64); cp_commit(); }
        const __nv_bfloat16* As = dynbf + (size_t)(kt&1)*STAGE_ELE;
        const __nv_bfloat16* Bs = As + TILE_A;
#pragma unroll
        for (int ks=0; ks<4; ks++){
            wmma::fragment<wmma::matrix_a,16,16,16,__nv_bfloat16,wmma::row_major> af[2];
            wmma::fragment<wmma::matrix_b,16,16,16,__nv_bfloat16,wmma::col_major> bf[2];
#pragma unroll
            for (int mf=0;mf<2;mf++)
                wmma::load_matrix_sync(af[mf], &As[(warp_m*32+mf*16)*TSTR + ks*16], TSTR);
#pragma unroll
            for (int nf=0;nf<2;nf++)
                wmma::load_matrix_sync(bf[nf], &Bs[(warp_n*32+nf*16)*TSTR + ks*16], TSTR);
#pragma unroll
            for (int mf=0;mf<2;mf++)
#pragma unroll
                for (int nf=0;nf<2;nf++)
                    wmma::mma_sync(acc[mf][nf], af[mf], bf[nf], acc[mf][nf]);
        }
    }
#undef H_LOAD
    __syncthreads();   // all compute done before smem reuse

    // fused epilogue: scale by ta[m], bias, relu, dot with fc2w over these 64 columns
    float* buf = (float*)dynbf;    // need 64*68*4 = 17.4KB <= 55KB
    int row = tid >> 2, q = tid & 3;
#pragma unroll
    for (int half=0; half<2; half++){
        if ((warp_m >> 1) == half){
            int rbase = (warp_m & 1)*32;
#pragma unroll
            for (int mf=0;mf<2;mf++)
#pragma unroll
                for (int nf=0;nf<2;nf++)
                    wmma::store_matrix_sync(&buf[(rbase+mf*16)*68 + warp_n*32+nf*16],
                                            acc[mf][nf], 68, wmma::mem_row_major);
        }
        __syncthreads();
        int lr = half*64 + row;
        float sc = sta[lr];
        float s = 0.f;
        int cbase = q*16;
#pragma unroll
        for (int c=0;c<16;c++){
            int gn = n0 + cbase + c;
            s += fmaxf(sc*buf[row*68 + cbase + c] + fc1b[gn], 0.f) * fc2w[gn];
        }
        s += __shfl_down_sync(0xffffffffu, s, 2);
        s += __shfl_down_sync(0xffffffffu, s, 1);
        if (q == 0) g_predpart[blockIdx.y*NM + m0 + lr] = s;
        __syncthreads();
    }
}

// ---------------- vision_CLS / text_CLS : grid (NB,3) ----------------
__global__ void cls_kernel(const float* __restrict__ vision, const float* __restrict__ text){
    int b = blockIdx.x;
    int d = blockIdx.y*256 + threadIdx.x;
    float av = 0.f, at = 0.f;
    const float* vb = vision + (size_t)b*NV*ND + d;
#pragma unroll 4
    for (int v=0; v<NV; v++) av += g_va[b*NV+v] * vb[(size_t)v*ND];
    const float* tb = text + (size_t)b*NT*ND + d;
#pragma unroll 4
    for (int t=0; t<NT; t++) at += g_ta[b*NT+t] * tb[(size_t)t*ND];
    g_vcls[b*ND+d] = av * (1.f/(float)NV);
    g_tcls[b*ND+d] = at * (1.f/(float)NT);
}

// ---------------- v_emb/t_emb = fc1(CLS)  (fp32, grid (NB,8)) ----------------
__global__ void emb_kernel(const float* __restrict__ fc1w, const float* __restrict__ fc1b){
    __shared__ float sv[ND], st[ND];
    int b = blockIdx.x, tid = threadIdx.x;
    int warp = tid >> 5, lane = tid & 31;
    for (int d=tid; d<ND; d+=256){ sv[d] = g_vcls[b*ND+d]; st[d] = g_tcls[b*ND+d]; }
    __syncthreads();
    int n0 = blockIdx.y*96 + warp*12;
#pragma unroll
    for (int k=0; k<12; k++){
        int n = n0 + k;
        const float* wr = fc1w + (size_t)n*ND;
        float a=0.f, cc=0.f;
        for (int d=lane; d<ND; d+=32){ float w = wr[d]; a += w*sv[d]; cc += w*st[d]; }
        a = wred(a); cc = wred(cc);
        if (lane == 0){
            g_vemb[b*ND+n] = a + fc1b[n];
            g_temb[b*ND+n] = cc + fc1b[n];
        }
    }
}

// ---------------- heads, contrast KL, semantic branch, textloss, outputs ----------------
__global__ __launch_bounds__(1024) void final_kernel(const float* __restrict__ fc2w,
                                                     const float* __restrict__ fc2b,
                                                     const float* __restrict__ fw,
                                                     const float* __restrict__ fb,
                                                     const float* __restrict__ sent,
                                                     const int* __restrict__ lens,
                                                     float* __restrict__ out){
    __shared__ float s_vs[32], s_ts[32], s_inv_nv[32], s_inv_nt[32];
    __shared__ float s_c[32][32], s_sim[32][32];
    __shared__ float s_crow[32], s_srow[32];
    __shared__ float s_var_v[ND], s_var_t[ND];
    __shared__ float s_red[32];
    __shared__ float s_tile[32][129];
    __shared__ float s_scal[2];
    __shared__ float s_loss[32];

    int tid = threadIdx.x;
    int warp = tid >> 5, lane = tid & 31;

    {
        int b = warp;
        float vs=0.f, ts=0.f, nv=0.f, nt=0.f;
        for (int d=lane; d<ND; d+=32){
            float ve = g_vemb[b*ND+d], te = g_temb[b*ND+d], w = fc2w[d];
            vs += fmaxf(ve,0.f)*w; ts += te*w; nv += ve*ve; nt += te*te;
        }
        vs = wred(vs); ts = wred(ts); nv = wred(nv); nt = wred(nt);
        if (lane == 0){
            s_vs[b] = vs + fc2b[0];
            s_ts[b] = ts + fc2b[0];
            s_inv_nv[b] = 1.f/fmaxf(sqrtf(nv), 1e-12f);
            s_inv_nt[b] = 1.f/fmaxf(sqrtf(nt), 1e-12f);
        }
    }
    // per-sample masked MSE (warp b) from pred partials
    {
        int b = warp;
        int len = lens[b];
        float s = 0.f;
        for (int t=lane; t<NT; t+=32){
            int m = b*NT + t;
            float p = fc2b[0];
#pragma unroll
            for (int pp=0; pp<NNB; pp++) p += g_predpart[pp*NM + m];
            if (sent[m] == 0.f) p = 0.f;
            if (t < len){
                float d = p - sent[m];
                s += d*d;
            }
        }
        s = wred(s);
        if (lane == 0) s_loss[b] = s / (float)len;
    }
    __syncthreads();

    int i = tid >> 5, j = tid & 31;
    float dot = 0.f;
    for (int kc=0; kc<ND; kc+=128){
        for (int e=tid; e<32*128; e+=1024){
            int r2 = e >> 7, c2 = e & 127;
            s_tile[r2][c2] = g_temb[r2*ND + kc + c2];
        }
        __syncthreads();
#pragma unroll 8
        for (int c=0;c<128;c++)
            dot += g_vemb[i*ND + kc + c] * s_tile[j][c];
        __syncthreads();
    }
    s_sim[i][j] = expf(dot * s_inv_nv[i] * s_inv_nt[j] * 5.0f);
    s_c[i][j]   = expf(-fabsf(s_vs[i] - s_ts[j]));
    __syncthreads();

    if (tid < 32){
        float cs=0.f, ss=0.f;
        for (int jj=0;jj<32;jj++){ cs += s_c[tid][jj]; ss += s_sim[tid][jj]; }
        s_crow[tid] = cs; s_srow[tid] = ss;
    }
    __syncthreads();

    {
        float cn = s_c[i][j]/s_crow[i];
        float sn = s_sim[i][j]/s_srow[i];
        float term = cn*(logf(cn) - logf(sn));
        term = wred(term);
        if (lane == 0) s_red[warp] = term;
        __syncthreads();
        if (tid < 32){
            float v = wred(s_red[tid]);
            if (tid == 0) out[32] = v * (1.f/32.f);
        }
    }
    __syncthreads();

    if (tid < ND){
        float sx=0.f, sx2=0.f;
        for (int b=0;b<32;b++){ float x = g_vcls[b*ND+tid]; sx += x; sx2 += x*x; }
        s_var_v[tid] = (sx2 - sx*sx*(1.f/32.f))*(1.f/31.f);
        sx=0.f; sx2=0.f;
        for (int b=0;b<32;b++){ float x = g_tcls[b*ND+tid]; sx += x; sx2 += x*x; }
        s_var_t[tid] = (sx2 - sx*sx*(1.f/32.f))*(1.f/31.f);
    }
    __syncthreads();
    {
        float v = (tid < ND) ? s_var_v[tid]*s_var_v[tid] : 0.f;
        v = wred(v);
        if (lane == 0) s_red[warp] = v;
        __syncthreads();
        if (tid < 32){
            float r = wred(s_red[tid]);
            if (tid == 0) s_scal[0] = 1.f/fmaxf(sqrtf(r), 1e-12f);
        }
        __syncthreads();
        float u = (tid < ND) ? s_var_t[tid]*s_var_t[tid] : 0.f;
        u = wred(u);
        if (lane == 0) s_red[warp] = u;
        __syncthreads();
        if (tid < 32){
            float r = wred(s_red[tid]);
            if (tid == 0) s_scal[1] = 1.f/fmaxf(sqrtf(r), 1e-12f);
        }
        __syncthreads();
        if (tid < ND){ s_var_v[tid] *= s_scal[0]; s_var_t[tid] *= s_scal[1]; }
    }
    __syncthreads();

    {
        int b = warp;
        float acc = 0.f;
        for (int d=lane; d<ND; d+=32){
            float sv  = g_vcls[b*ND+d]*(1.f + s_var_v[d]);
            float st2 = g_tcls[b*ND+d]*(1.f + s_var_t[d]);
            float fcls = 0.5f*(sv*st2 + g_vemb[b*ND+d]*g_temb[b*ND+d]);
            acc += fcls*fw[d];
        }
        acc = wred(acc);
        if (lane == 0)
            out[b] = acc + fb[0] + 0.1f*fabsf(s_ts[b] - s_vs[b]) - 0.5f;
    }

    if (tid < 32){
        float v = wred(s_loss[tid]);
        if (tid == 0) out[33] = v * (1.f/32.f);
    }
}

// ---------------- launch ----------------
extern "C" void kernel_launch(void* const* d_in, const int* in_sizes, int n_in,
                              void* d_out, int out_size){
    const float* vision = (const float*)d_in[0];
    const float* text   = (const float*)d_in[1];
    const float* sent   = (const float*)d_in[2];
    const int*   lens   = (const int*)  d_in[3];
    const float* fc1_w  = (const float*)d_in[4];
    const float* fc1_b  = (const float*)d_in[5];
    const float* fc2_w  = (const float*)d_in[6];
    const float* fc2_b  = (const float*)d_in[7];
    const float* c1w    = (const float*)d_in[8];
    const float* c1b    = (const float*)d_in[9];
    const float* c2w    = (const float*)d_in[10];
    const float* c2b    = (const float*)d_in[11];
    const float* fw     = (const float*)d_in[12];
    const float* fb     = (const float*)d_in[13];
    float* out = (float*)d_out;

    cudaFuncSetAttribute(gemm_amap_kernel, cudaFuncAttributeMaxDynamicSharedMemorySize, G_DYN);
    cudaFuncSetAttribute(gemm_h_kernel,    cudaFuncAttributeMaxDynamicSharedMemorySize, G_DYN);

    convert_prep_kernel<<<NCVT+1, 256>>>(text, vision, fc1_w, c1w, c1b, c2w, c2b);
    gemm_amap_kernel<<<dim3(2,8,NB), 256, G_DYN>>>();
    conv_fused_kernel<<<dim3(NCH,NB), 256>>>();
    gemm_h_kernel<<<dim3(128,NNB), 256, G_DYN>>>(fc1_b, fc2_w);   // 4th launch -> ncu slot
    cls_kernel<<<dim3(NB,3), 256>>>(vision, text);
    emb_kernel<<<dim3(NB,8), 256>>>(fc1_w, fc1_b);
    final_kernel<<<1, 1024>>>(fc2_w, fc2_b, fw, fb, sent, lens, out);
}

// round 13
// speedup vs baseline: 1.4366x; 1.4366x over previous
#include <cuda_runtime.h>
#include <cuda_bf16.h>
#include <cstdint>
#include <mma.h>
using namespace nvcuda;

#define NB 32
#define NV 197
#define NVP 256
#define NT 512
#define ND 768
#define NM (NB*NT)       // 16384
#define NNB 6            // n-blocks in gemm_h (768/128)
#define NCH 13           // conv row-chunks of 16
#define NCLS 8           // cls partial chunks

// ---------------- device scratch ----------------
static __device__ float g_amap[NB*NVP*NT];
static __device__ float g_tapart[NCH*NB*NT];
static __device__ float g_ta[NM];
static __device__ float g_va[NB*NV];
static __device__ float g_clspart_v[NCLS*NB*ND];
static __device__ float g_clspart_t[NCLS*NB*ND];
static __device__ float g_vcls[NB*ND];
static __device__ float g_tcls[NB*ND];
static __device__ float g_temb[NB*ND];
static __device__ float g_vemb[NB*ND];
static __device__ float g_predpart[NNB*NM];
static __device__ float g_keff[9][25];
static __device__ float g_kbias[9];
static __device__ __nv_bfloat16 g_textbf[NM*ND];
static __device__ __nv_bfloat16 g_visbf[NB*NV*ND];
static __device__ __nv_bfloat16 g_w1bf[ND*ND];

__device__ __forceinline__ float wred(float v){
#pragma unroll
    for (int o = 16; o; o >>= 1) v += __shfl_xor_sync(0xffffffffu, v, o);
    return v;
}
__device__ __forceinline__ float sigmoidf(float x){ return 1.f/(1.f + expf(-x)); }

// ---- cp.async helpers ----
__device__ __forceinline__ void cp16(void* s, const void* g){
    unsigned int sa = (unsigned int)__cvta_generic_to_shared(s);
    asm volatile("cp.async.cg.shared.global [%0], [%1], 16;" :: "r"(sa), "l"(g));
}
__device__ __forceinline__ void cp_commit(){ asm volatile("cp.async.commit_group;"); }
template<int N> __device__ __forceinline__ void cp_wait(){
    asm volatile("cp.async.wait_group %0;" :: "n"(N));
}

// BK=64 tile geometry (R9 config): stride 72 bf16 (=144B)
#define TSTR 72
#define TILE_ELE (128*TSTR)                 // per matrix per stage (bf16 elements)
#define G_DYN (2*2*TILE_ELE*2)              // 73,728 B dynamic smem per GEMM block

// ---------------- fp32 -> bf16 conversion + conv composition (merged) ----------------
#define CT1 (NM*ND/4)
#define CT2 (CT1 + NB*NV*ND/4)
#define CT3 (CT2 + ND*ND/4)
#define NCVT (CT3/256)
__global__ void convert_prep_kernel(const float* __restrict__ text,
                                    const float* __restrict__ vision,
                                    const float* __restrict__ fc1w,
                                    const float* __restrict__ w1, const float* __restrict__ b1,
                                    const float* __restrict__ w2, const float* __restrict__ b2){
    if (blockIdx.x < NCVT){
        int p = blockIdx.x*256 + threadIdx.x;
        const float* src; __nv_bfloat16* dst; int off;
        if (p < CT1){ src = text; dst = g_textbf; off = p; }
        else if (p < CT2){ src = vision; dst = g_visbf; off = p - CT1; }
        else { src = fc1w; dst = g_w1bf; off = p - CT2; }
        float4 v = ((const float4*)src)[off];
        __nv_bfloat162* d2 = (__nv_bfloat162*)dst;
        d2[off*2]   = __floats2bfloat162_rn(v.x, v.y);
        d2[off*2+1] = __floats2bfloat162_rn(v.z, v.w);
        return;
    }
    int tid = threadIdx.x;
    if (tid < 225){
        int var = tid/25, uv = tid%25, u = uv/5, v = uv%5;
        int ri = var/3, rj = var%3;
        float s = 0.f;
        for (int d1=0; d1<3; d1++){
            if ((ri==0 && d1==0) || (ri==2 && d1==2)) continue;
            int d2 = u - d1; if (d2 < 0 || d2 > 2) continue;
            for (int e1=0; e1<3; e1++){
                if ((rj==0 && e1==0) || (rj==2 && e1==2)) continue;
                int e2 = v - e1; if (e2 < 0 || e2 > 2) continue;
                for (int c=0; c<64; c++)
                    s += w2[c*9 + d1*3 + e1] * w1[c*9 + d2*3 + e2];
            }
        }
        g_keff[var][uv] = s;
    } else if (tid < 234){
        int var = tid - 225;
        int ri = var/3, rj = var%3;
        float s = b2[0];
        for (int c=0; c<64; c++){
            float t = 0.f;
            for (int d1=0; d1<3; d1++){
                if ((ri==0 && d1==0) || (ri==2 && d1==2)) continue;
                for (int e1=0; e1<3; e1++){
                    if ((rj==0 && e1==0) || (rj==2 && e1==2)) continue;
                    t += w2[c*9 + d1*3 + e1];
                }
            }
            s += b1[c]*t;
        }
        g_kbias[var] = s;
    }
}

// ============ bf16 wmma GEMM 1 (R9 config: 128x128, BK=64, occ2): amap = vision . text^T ============
__global__ __launch_bounds__(256,2) void gemm_amap_kernel(){
    extern __shared__ __align__(16) __nv_bfloat16 dynbf[];
    int b  = blockIdx.z;
    const __nv_bfloat16* A  = g_visbf  + (size_t)b*NV*ND;
    const __nv_bfloat16* Bp = g_textbf + (size_t)b*NT*ND;
    int m0 = blockIdx.x*128, n0 = blockIdx.y*128;
    int tid = threadIdx.x, wid = tid >> 5;
    int warp_m = wid >> 1, warp_n = wid & 1;

    wmma::fragment<wmma::accumulator,16,16,16,float> acc[2][4];
#pragma unroll
    for (int mf=0;mf<2;mf++)
#pragma unroll
        for (int nf=0;nf<4;nf++) wmma::fill_fragment(acc[mf][nf], 0.f);

    const int NKT = ND/64;   // 12
#define AMAP_LOAD(s, k0)  do {                                               \
    __nv_bfloat16* As_ = dynbf + (size_t)((s)*2+0)*TILE_ELE;                 \
    __nv_bfloat16* Bs_ = dynbf + (size_t)((s)*2+1)*TILE_ELE;                 \
    _Pragma("unroll")                                                        \
    for (int l=0; l<4; l++){                                                 \
        int q = tid + l*256;                                                 \
        int r = q >> 3, c8 = q & 7;                                          \
        int gm = m0 + r; if (gm > NV-1) gm = NV-1;                           \
        cp16(&As_[r*TSTR + c8*8], &A [(size_t)gm*ND + (k0) + c8*8]);         \
        cp16(&Bs_[r*TSTR + c8*8], &Bp[(size_t)(n0+r)*ND + (k0) + c8*8]);     \
    } } while(0)

    AMAP_LOAD(0, 0);
    cp_commit();
    for (int kt=0; kt<NKT; kt++){
        cp_wait<0>();
        __syncthreads();
        if (kt+1 < NKT){ AMAP_LOAD((kt+1)&1, (kt+1)*64); cp_commit(); }
        const __nv_bfloat16* As = dynbf + (size_t)((kt&1)*2+0)*TILE_ELE;
        const __nv_bfloat16* Bs = dynbf + (size_t)((kt&1)*2+1)*TILE_ELE;
#pragma unroll
        for (int ks=0; ks<4; ks++){
            wmma::fragment<wmma::matrix_a,16,16,16,__nv_bfloat16,wmma::row_major> af[2];
            wmma::fragment<wmma::matrix_b,16,16,16,__nv_bfloat16,wmma::col_major> bf[4];
#pragma unroll
            for (int mf=0;mf<2;mf++)
                wmma::load_matrix_sync(af[mf], &As[(warp_m*32+mf*16)*TSTR + ks*16], TSTR);
#pragma unroll
            for (int nf=0;nf<4;nf++)
                wmma::load_matrix_sync(bf[nf], &Bs[(warp_n*64+nf*16)*TSTR + ks*16], TSTR);
#pragma unroll
            for (int mf=0;mf<2;mf++)
#pragma unroll
                for (int nf=0;nf<4;nf++)
                    wmma::mma_sync(acc[mf][nf], af[mf], bf[nf], acc[mf][nf]);
        }
    }
#undef AMAP_LOAD
    float* C = g_amap + (size_t)b*NVP*NT;
#pragma unroll
    for (int mf=0;mf<2;mf++)
#pragma unroll
        for (int nf=0;nf<4;nf++)
            wmma::store_matrix_sync(&C[(size_t)(m0+warp_m*32+mf*16)*NT + n0+warp_n*64+nf*16],
                                    acc[mf][nf], NT, wmma::mem_row_major);
}

// ============ fused 5x5 conv + relu + va + ta partials ============
__global__ __launch_bounds__(256) void conv_fused_kernel(){
    __shared__ float smz[20][NT];
    __shared__ float kvs[9][25];
    __shared__ float kbs[9];
    __shared__ float rowred[16][8];
    int c = blockIdx.x;
    int b = blockIdx.y;
    int tid = threadIdx.x;
    int warp = tid >> 5, lane = tid & 31;
    if (tid < 225) ((float*)kvs)[tid] = ((const float*)g_keff)[tid];
    else if (tid >= 240 && tid < 249) kbs[tid-240] = g_kbias[tid-240];

    int i0 = c*16;
    const float* base = g_amap + (size_t)b*NVP*NT;
#pragma unroll
    for (int l=0; l<10; l++){
        int e = tid + l*256;
        int rr = e >> 7, c4 = e & 127;
        int gi = i0 - 2 + rr;
        float4 v = make_float4(0.f,0.f,0.f,0.f);
        if (gi >= 0 && gi < NV) v = *(const float4*)&base[(size_t)gi*NT + c4*4];
        *(float4*)&smz[rr][c4*4] = v;
    }
    __syncthreads();

    float rowpart[16];
#pragma unroll
    for (int rr=0;rr<16;rr++) rowpart[rr] = 0.f;

#pragma unroll
    for (int jj=0; jj<2; jj++){
        int j = tid + jj*256;
        int rj = (j==0) ? 0 : ((j==NT-1) ? 2 : 1);
        float kreg[25];
#pragma unroll
        for (int t=0;t<25;t++) kreg[t] = kvs[3+rj][t];
        float kbmid = kbs[3+rj];

        float w[5][5];
#pragma unroll
        for (int u=0;u<4;u++)
#pragma unroll
            for (int v=0;v<5;v++){
                int j2 = j + v - 2;
                w[u][v] = (j2>=0 && j2<NT) ? smz[u][j2] : 0.f;
            }
        float colsum = 0.f;
#pragma unroll
        for (int rr=0; rr<16; rr++){
#pragma unroll
            for (int v=0;v<5;v++){
                int j2 = j + v - 2;
                w[4][v] = (j2>=0 && j2<NT) ? smz[rr+4][j2] : 0.f;
            }
            int i = i0 + rr;
            if (i < NV){
                float s;
                if (i==0 || i==NV-1){
                    int var = ((i==0)?0:6) + rj;
                    s = kbs[var];
                    const float* kp = kvs[var];
#pragma unroll
                    for (int u=0;u<5;u++)
#pragma unroll
                        for (int v=0;v<5;v++) s += kp[u*5+v]*w[u][v];
                } else {
                    s = kbmid;
#pragma unroll
                    for (int u=0;u<5;u++)
#pragma unroll
                        for (int v=0;v<5;v++) s += kreg[u*5+v]*w[u][v];
                }
                s = fmaxf(s, 0.f);
                colsum += s;
                rowpart[rr] += s;
            }
#pragma unroll
            for (int u=0;u<4;u++)
#pragma unroll
                for (int v=0;v<5;v++) w[u][v] = w[u+1][v];
        }
        g_tapart[(size_t)(c*NB + b)*NT + j] = colsum;
    }
#pragma unroll
    for (int rr=0; rr<16; rr++){
        float v = wred(rowpart[rr]);
        if (lane == 0) rowred[rr][warp] = v;
    }
    __syncthreads();
    if (tid < 128){
        int rr = tid >> 3, slot = tid & 7;
        float v = rowred[rr][slot];
        v += __shfl_down_sync(0xffffffffu, v, 4, 8);
        v += __shfl_down_sync(0xffffffffu, v, 2, 8);
        v += __shfl_down_sync(0xffffffffu, v, 1, 8);
        if (slot == 0){
            int gi = i0 + rr;
            if (gi < NV) g_va[b*NV + gi] = sigmoidf(v * (1.f/(float)NT));
        }
    }
}

// ============ bf16 wmma GEMM 2 (R9 config) + inline ta + pred epilogue ============
__global__ __launch_bounds__(256,2) void gemm_h_kernel(const float* __restrict__ fc1b,
                                                       const float* __restrict__ fc2w){
    extern __shared__ __align__(16) __nv_bfloat16 dynbf[];
    __shared__ float sta[128];
    int m0 = blockIdx.x*128, n0 = blockIdx.y*128;
    int tid = threadIdx.x, wid = tid >> 5;
    int warp_m = wid >> 1, warp_n = wid & 1;

    {
        int bb = m0 / NT, t0 = m0 % NT;
        if (tid < 128){
            float s = 0.f;
#pragma unroll
            for (int c=0;c<NCH;c++) s += g_tapart[(size_t)(c*NB + bb)*NT + t0 + tid];
            float v = sigmoidf(s * (1.f/(float)NV));
            sta[tid] = v;
            if (blockIdx.y == 0) g_ta[m0 + tid] = v;
        }
    }

    wmma::fragment<wmma::accumulator,16,16,16,float> acc[2][4];
#pragma unroll
    for (int mf=0;mf<2;mf++)
#pragma unroll
        for (int nf=0;nf<4;nf++) wmma::fill_fragment(acc[mf][nf], 0.f);

    const int NKT = ND/64;   // 12
#define H_LOAD(s, k0)  do {                                                    \
    __nv_bfloat16* As_ = dynbf + (size_t)((s)*2+0)*TILE_ELE;                   \
    __nv_bfloat16* Bs_ = dynbf + (size_t)((s)*2+1)*TILE_ELE;                   \
    _Pragma("unroll")                                                          \
    for (int l=0; l<4; l++){                                                   \
        int q = tid + l*256;                                                   \
        int r = q >> 3, c8 = q & 7;                                            \
        cp16(&As_[r*TSTR + c8*8], &g_textbf[(size_t)(m0+r)*ND + (k0) + c8*8]); \
        cp16(&Bs_[r*TSTR + c8*8], &g_w1bf  [(size_t)(n0+r)*ND + (k0) + c8*8]); \
    } } while(0)

    H_LOAD(0, 0);
    cp_commit();
    for (int kt=0; kt<NKT; kt++){
        cp_wait<0>();
        __syncthreads();
        if (kt+1 < NKT){ H_LOAD((kt+1)&1, (kt+1)*64); cp_commit(); }
        const __nv_bfloat16* As = dynbf + (size_t)((kt&1)*2+0)*TILE_ELE;
        const __nv_bfloat16* Bs = dynbf + (size_t)((kt&1)*2+1)*TILE_ELE;
#pragma unroll
        for (int ks=0; ks<4; ks++){
            wmma::fragment<wmma::matrix_a,16,16,16,__nv_bfloat16,wmma::row_major> af[2];
            wmma::fragment<wmma::matrix_b,16,16,16,__nv_bfloat16,wmma::col_major> bf[4];
#pragma unroll
            for (int mf=0;mf<2;mf++)
                wmma::load_matrix_sync(af[mf], &As[(warp_m*32+mf*16)*TSTR + ks*16], TSTR);
#pragma unroll
            for (int nf=0;nf<4;nf++)
                wmma::load_matrix_sync(bf[nf], &Bs[(warp_n*64+nf*16)*TSTR + ks*16], TSTR);
#pragma unroll
            for (int mf=0;mf<2;mf++)
#pragma unroll
                for (int nf=0;nf<4;nf++)
                    wmma::mma_sync(acc[mf][nf], af[mf], bf[nf], acc[mf][nf]);
        }
    }
#undef H_LOAD
    __syncthreads();

    float* buf = (float*)dynbf;    // 64*132*4 = 33.8KB <= 72KB
    int row = tid >> 2, q = tid & 3;
#pragma unroll
    for (int half=0; half<2; half++){
        if ((warp_m >> 1) == half){
            int rbase = (warp_m & 1)*32;
#pragma unroll
            for (int mf=0;mf<2;mf++)
#pragma unroll
                for (int nf=0;nf<4;nf++)
                    wmma::store_matrix_sync(&buf[(rbase+mf*16)*132 + warp_n*64+nf*16],
                                            acc[mf][nf], 132, wmma::mem_row_major);
        }
        __syncthreads();
        int lr = half*64 + row;
        float sc = sta[lr];
        float s = 0.f;
        int cbase = q*32;
#pragma unroll
        for (int c=0;c<32;c++){
            int gn = n0 + cbase + c;
            s += fmaxf(sc*buf[row*132 + cbase + c] + fc1b[gn], 0.f) * fc2w[gn];
        }
        s += __shfl_down_sync(0xffffffffu, s, 2);
        s += __shfl_down_sync(0xffffffffu, s, 1);
        if (q == 0) g_predpart[blockIdx.y*NM + m0 + lr] = s;
        __syncthreads();
    }
}

// ---------------- cls partials : grid (NB, 3, NCLS) ----------------
__global__ void cls_part_kernel(const float* __restrict__ vision, const float* __restrict__ text){
    int b = blockIdx.x;
    int d = blockIdx.y*256 + threadIdx.x;
    int z = blockIdx.z;
    int v0 = z*25, v1 = (z==NCLS-1) ? NV : (z+1)*25;
    float av = 0.f;
    const float* vb = vision + (size_t)b*NV*ND + d;
#pragma unroll 4
    for (int v=v0; v<v1; v++) av += g_va[b*NV+v] * vb[(size_t)v*ND];
    int t0 = z*64;
    float at = 0.f;
    const float* tb = text + (size_t)b*NT*ND + d;
#pragma unroll 4
    for (int t=t0; t<t0+64; t++) at += g_ta[b*NT+t] * tb[(size_t)t*ND];
    g_clspart_v[(size_t)(z*NB + b)*ND + d] = av;
    g_clspart_t[(size_t)(z*NB + b)*ND + d] = at;
}

// ---------------- cls reduce : grid (NB, 3) ----------------
__global__ void cls_reduce_kernel(){
    int b = blockIdx.x;
    int d = blockIdx.y*256 + threadIdx.x;
    float av = 0.f, at = 0.f;
#pragma unroll
    for (int z=0; z<NCLS; z++){
        av += g_clspart_v[(size_t)(z*NB + b)*ND + d];
        at += g_clspart_t[(size_t)(z*NB + b)*ND + d];
    }
    g_vcls[b*ND+d] = av * (1.f/(float)NV);
    g_tcls[b*ND+d] = at * (1.f/(float)NT);
}

// ---------------- v_emb/t_emb = fc1(CLS)  (fp32, grid (NB,24), 4 n per warp) ----------------
__global__ void emb_kernel(const float* __restrict__ fc1w, const float* __restrict__ fc1b){
    __shared__ float sv[ND], st[ND];
    int b = blockIdx.x, tid = threadIdx.x;
    int warp = tid >> 5, lane = tid & 31;
    for (int d=tid; d<ND; d+=256){ sv[d] = g_vcls[b*ND+d]; st[d] = g_tcls[b*ND+d]; }
    __syncthreads();
    int n0 = blockIdx.y*32 + warp*4;
#pragma unroll
    for (int k=0; k<4; k++){
        int n = n0 + k;
        const float* wr = fc1w + (size_t)n*ND;
        float a=0.f, cc=0.f;
        for (int d=lane; d<ND; d+=32){ float w = wr[d]; a += w*sv[d]; cc += w*st[d]; }
        a = wred(a); cc = wred(cc);
        if (lane == 0){
            g_vemb[b*ND+n] = a + fc1b[n];
            g_temb[b*ND+n] = cc + fc1b[n];
        }
    }
}

// ---------------- heads, contrast KL, semantic branch, textloss, outputs ----------------
__global__ __launch_bounds__(1024) void final_kernel(const float* __restrict__ fc2w,
                                                     const float* __restrict__ fc2b,
                                                     const float* __restrict__ fw,
                                                     const float* __restrict__ fb,
                                                     const float* __restrict__ sent,
                                                     const int* __restrict__ lens,
                                                     float* __restrict__ out){
    __shared__ float s_vs[32], s_ts[32], s_inv_nv[32], s_inv_nt[32];
    __shared__ float s_c[32][32], s_sim[32][32];
    __shared__ float s_crow[32], s_srow[32];
    __shared__ float s_var_v[ND], s_var_t[ND];
    __shared__ float s_red[32];
    __shared__ float s_tile[32][129];
    __shared__ float s_scal[2];
    __shared__ float s_loss[32];

    int tid = threadIdx.x;
    int warp = tid >> 5, lane = tid & 31;

    {
        int b = warp;
        float vs=0.f, ts=0.f, nv=0.f, nt=0.f;
        for (int d=lane; d<ND; d+=32){
            float ve = g_vemb[b*ND+d], te = g_temb[b*ND+d], w = fc2w[d];
            vs += fmaxf(ve,0.f)*w; ts += te*w; nv += ve*ve; nt += te*te;
        }
        vs = wred(vs); ts = wred(ts); nv = wred(nv); nt = wred(nt);
        if (lane == 0){
            s_vs[b] = vs + fc2b[0];
            s_ts[b] = ts + fc2b[0];
            s_inv_nv[b] = 1.f/fmaxf(sqrtf(nv), 1e-12f);
            s_inv_nt[b] = 1.f/fmaxf(sqrtf(nt), 1e-12f);
        }
    }
    {
        int b = warp;
        int len = lens[b];
        float s = 0.f;
        for (int t=lane; t<NT; t+=32){
            int m = b*NT + t;
            float p = fc2b[0];
#pragma unroll
            for (int pp=0; pp<NNB; pp++) p += g_predpart[pp*NM + m];
            if (sent[m] == 0.f) p = 0.f;
            if (t < len){
                float d = p - sent[m];
                s += d*d;
            }
        }
        s = wred(s);
        if (lane == 0) s_loss[b] = s / (float)len;
    }
    __syncthreads();

    int i = tid >> 5, j = tid & 31;
    float dot = 0.f;
    for (int kc=0; kc<ND; kc+=128){
        for (int e=tid; e<32*128; e+=1024){
            int r2 = e >> 7, c2 = e & 127;
            s_tile[r2][c2] = g_temb[r2*ND + kc + c2];
        }
        __syncthreads();
#pragma unroll 8
        for (int c=0;c<128;c++)
            dot += g_vemb[i*ND + kc + c] * s_tile[j][c];
        __syncthreads();
    }
    s_sim[i][j] = expf(dot * s_inv_nv[i] * s_inv_nt[j] * 5.0f);
    s_c[i][j]   = expf(-fabsf(s_vs[i] - s_ts[j]));
    __syncthreads();

    if (tid < 32){
        float cs=0.f, ss=0.f;
        for (int jj=0;jj<32;jj++){ cs += s_c[tid][jj]; ss += s_sim[tid][jj]; }
        s_crow[tid] = cs; s_srow[tid] = ss;
    }
    __syncthreads();

    {
        float cn = s_c[i][j]/s_crow[i];
        float sn = s_sim[i][j]/s_srow[i];
        float term = cn*(logf(cn) - logf(sn));
        term = wred(term);
        if (lane == 0) s_red[warp] = term;
        __syncthreads();
        if (tid < 32){
            float v = wred(s_red[tid]);
            if (tid == 0) out[32] = v * (1.f/32.f);
        }
    }
    __syncthreads();

    if (tid < ND){
        float sx=0.f, sx2=0.f;
        for (int b=0;b<32;b++){ float x = g_vcls[b*ND+tid]; sx += x; sx2 += x*x; }
        s_var_v[tid] = (sx2 - sx*sx*(1.f/32.f))*(1.f/31.f);
        sx=0.f; sx2=0.f;
        for (int b=0;b<32;b++){ float x = g_tcls[b*ND+tid]; sx += x; sx2 += x*x; }
        s_var_t[tid] = (sx2 - sx*sx*(1.f/32.f))*(1.f/31.f);
    }
    __syncthreads();
    {
        float v = (tid < ND) ? s_var_v[tid]*s_var_v[tid] : 0.f;
        v = wred(v);
        if (lane == 0) s_red[warp] = v;
        __syncthreads();
        if (tid < 32){
            float r = wred(s_red[tid]);
            if (tid == 0) s_scal[0] = 1.f/fmaxf(sqrtf(r), 1e-12f);
        }
        __syncthreads();
        float u = (tid < ND) ? s_var_t[tid]*s_var_t[tid] : 0.f;
        u = wred(u);
        if (lane == 0) s_red[warp] = u;
        __syncthreads();
        if (tid < 32){
            float r = wred(s_red[tid]);
            if (tid == 0) s_scal[1] = 1.f/fmaxf(sqrtf(r), 1e-12f);
        }
        __syncthreads();
        if (tid < ND){ s_var_v[tid] *= s_scal[0]; s_var_t[tid] *= s_scal[1]; }
    }
    __syncthreads();

    {
        int b = warp;
        float acc = 0.f;
        for (int d=lane; d<ND; d+=32){
            float sv  = g_vcls[b*ND+d]*(1.f + s_var_v[d]);
            float st2 = g_tcls[b*ND+d]*(1.f + s_var_t[d]);
            float fcls = 0.5f*(sv*st2 + g_vemb[b*ND+d]*g_temb[b*ND+d]);
            acc += fcls*fw[d];
        }
        acc = wred(acc);
        if (lane == 0)
            out[b] = acc + fb[0] + 0.1f*fabsf(s_ts[b] - s_vs[b]) - 0.5f;
    }

    if (tid < 32){
        float v = wred(s_loss[tid]);
        if (tid == 0) out[33] = v * (1.f/32.f);
    }
}

// ---------------- launch ----------------
extern "C" void kernel_launch(void* const* d_in, const int* in_sizes, int n_in,
                              void* d_out, int out_size){
    const float* vision = (const float*)d_in[0];
    const float* text   = (const float*)d_in[1];
    const float* sent   = (const float*)d_in[2];
    const int*   lens   = (const int*)d_in[3];
    const float* fc1_w  = (const float*)d_in[4];
    const float* fc1_b  = (const float*)d_in[5];
    const float* fc2_w  = (const float*)d_in[6];
    const float* fc2_b  = (const float*)d_in[7];
    const float* c1w    = (const float*)d_in[8];
    const float* c1b    = (const float*)d_in[9];
    const float* c2w    = (const float*)d_in[10];
    const float* c2b    = (const float*)d_in[11];
    const float* fw     = (const float*)d_in[12];
    const float* fb     = (const float*)d_in[13];
    float* out = (float*)d_out;

    cudaFuncSetAttribute(gemm_amap_kernel, cudaFuncAttributeMaxDynamicSharedMemorySize, G_DYN);
    cudaFuncSetAttribute(gemm_h_kernel,    cudaFuncAttributeMaxDynamicSharedMemorySize, G_DYN);

    convert_prep_kernel<<<NCVT+1, 256>>>(text, vision, fc1_w, c1w, c1b, c2w, c2b);
    gemm_amap_kernel<<<dim3(2,4,NB), 256, G_DYN>>>();
    conv_fused_kernel<<<dim3(NCH,NB), 256>>>();
    gemm_h_kernel<<<dim3(128,NNB), 256, G_DYN>>>(fc1_b, fc2_w);   // 4th launch -> ncu slot
    cls_part_kernel<<<dim3(NB,3,NCLS), 256>>>(vision, text);
    cls_reduce_kernel<<<dim3(NB,3), 256>>>();
    emb_kernel<<<dim3(NB,24), 256>>>(fc1_w, fc1_b);
    final_kernel<<<1, 1024>>>(fc2_w, fc2_b, fw, fb, sent, lens, out);
}